// round 12
// baseline (speedup 1.0000x reference)
#include <cuda_runtime.h>
#include <cuda_fp16.h>

#define N_T1 168            // dow(7) * sex(2) * month(12)
#define N_T2 744            // time(24) * day(31)
#define N_T3 100            // age
#define NE   (N_T1 + N_T2 + N_T3)   // 1012
#define NUM_DEST 100000

// Pre-projected fused tables in fp16, DUPLICATED per entry:
// entry e occupies 128 B: copy A at [e*128, e*128+64)    -> smem banks 0..15
//                         copy B at [e*128+64, e*128+128) -> smem banks 16..31
__device__ uint4 g_projh[NE * 8];        // NE * 128 B
// Item table converted to fp16: row = 32 halves = 64 B = 4 uint4.
__device__ uint4 g_itemh[NUM_DEST * 4];  // 6.4 MB

#define CV_THREADS (NUM_DEST * 8)            // one thread per 4 floats
#define CV_BLOCKS  ((CV_THREADS + 255) / 256)
#define PRE_THREADS (NE * 32)
#define PRE_BLOCKS ((PRE_THREADS + 255) / 256)

__global__ __launch_bounds__(256)
void prep_kernel(const float* __restrict__ emb_dow,
                 const float* __restrict__ emb_time,
                 const float* __restrict__ emb_sex,
                 const float* __restrict__ emb_age,
                 const float* __restrict__ emb_month,
                 const float* __restrict__ emb_day,
                 const float* __restrict__ W,
                 const float* __restrict__ b,
                 const float4* __restrict__ item4f) {
    if (blockIdx.x < CV_BLOCKS) {
        // ---- Item table fp32 -> fp16 (one thread per float4) ----
        int t = blockIdx.x * 256 + threadIdx.x;
        if (t >= CV_THREADS) return;
        float4 f = item4f[t];
        __half2 lo = __floats2half2_rn(f.x, f.y);
        __half2 hi = __floats2half2_rn(f.z, f.w);
        reinterpret_cast<uint2*>(g_itemh)[t] =
            make_uint2(*reinterpret_cast<uint*>(&lo), *reinterpret_cast<uint*>(&hi));
        return;
    }
    // ---- Pre-projected fused user tables ----
    int t = (blockIdx.x - CV_BLOCKS) * 256 + threadIdx.x;
    if (t >= PRE_THREADS) return;
    int e = t >> 5;
    int f = t & 31;
    float v = 0.f;
    // W row layout follows concat order: dow[0:4) time[4:8) sex[8:12) age[12:16) month[16:20) day[20:24)
    if (e < N_T1) {
        int d = e / 24, rem = e % 24;
        int s = rem / 12, m = rem % 12;
        #pragma unroll
        for (int j = 0; j < 4; j++) {
            v = fmaf(emb_dow[d * 4 + j],   W[(0 + j) * 32 + f], v);
            v = fmaf(emb_sex[s * 4 + j],   W[(8 + j) * 32 + f], v);
            v = fmaf(emb_month[m * 4 + j], W[(16 + j) * 32 + f], v);
        }
    } else if (e < N_T1 + N_T2) {
        int e2 = e - N_T1;
        int tm = e2 / 31, dy = e2 % 31;
        #pragma unroll
        for (int j = 0; j < 4; j++) {
            v = fmaf(emb_time[tm * 4 + j], W[(4 + j) * 32 + f], v);
            v = fmaf(emb_day[dy * 4 + j],  W[(20 + j) * 32 + f], v);
        }
    } else {
        int a = e - (N_T1 + N_T2);
        v = b[f];
        #pragma unroll
        for (int j = 0; j < 4; j++)
            v = fmaf(emb_age[a * 4 + j], W[(12 + j) * 32 + f], v);
    }
    __half hv = __float2half_rn(v);
    __half* base = reinterpret_cast<__half*>(g_projh) + e * 64;
    base[f]      = hv;   // copy A
    base[32 + f] = hv;   // copy B
}

__global__ __launch_bounds__(1024, 1)
void mf_main_kernel(const int* __restrict__ dow,
                    const int* __restrict__ tim,
                    const int* __restrict__ sex,
                    const int* __restrict__ age,
                    const int* __restrict__ month,
                    const int* __restrict__ day,
                    const int* __restrict__ dest,
                    float* __restrict__ out,
                    int n) {
    extern __shared__ uint4 sp[];   // table (NE*8 uint4) + per-warp idx staging
    // Staging: 32 warps x 64 rows x int2(pk,dd) = 16 KB
    int2* stage = reinterpret_cast<int2*>(sp + NE * 8);

    for (int i = threadIdx.x; i < NE * 8; i += blockDim.x)
        sp[i] = g_projh[i];
    __syncthreads();

    const char* spb = reinterpret_cast<const char*>(sp);

    const int lane = threadIdx.x & 31;
    const int warp = threadIdx.x >> 5;
    const int sub  = lane & 3;        // position within 4-lane group (8 halves each)
    const int grp  = lane >> 2;       // group id 0..7 (contiguous lanes)
    // Dup tables: adjacent groups have opposite parity -> each 8-lane LDS phase
    // hits disjoint bank halves: deterministically conflict-free.
    const int par  = (grp & 1) * 64 + sub * 16;

    int2* stw  = stage + warp * 64;              // this warp's 64 staging slots
    uint4* stw4 = reinterpret_cast<uint4*>(stw); // 16B view (2 rows per slot)

    const int warpsTotal = gridDim.x * (blockDim.x >> 5);
    const int gwarp = blockIdx.x * (blockDim.x >> 5) + warp;

    const __half2 zero2 = __float2half2_rn(0.f);

    for (int base = gwarp * 64; base < n; base += warpsTotal * 64) {
        // ---- Phase A: 64 rows of indices per outer (one DRAM-latency event) ----
        int pk0, dd0, pk1, dd1;
        if (base + 64 <= n) {
            // Fully in-bounds: vectorized LDG.64 (lane covers rows 2l, 2l+1).
            int2 vdw = reinterpret_cast<const int2*>(dow   + base)[lane];
            int2 vtm = reinterpret_cast<const int2*>(tim   + base)[lane];
            int2 vsx = reinterpret_cast<const int2*>(sex   + base)[lane];
            int2 vag = reinterpret_cast<const int2*>(age   + base)[lane];
            int2 vmo = reinterpret_cast<const int2*>(month + base)[lane];
            int2 vdy = reinterpret_cast<const int2*>(day   + base)[lane];
            int2 vds = reinterpret_cast<const int2*>(dest  + base)[lane];
            pk0 = (vdw.x * 24 + vsx.x * 12 + vmo.x)
                | ((vtm.x * 31 + vdy.x) << 8) | (vag.x << 18);
            pk1 = (vdw.y * 24 + vsx.y * 12 + vmo.y)
                | ((vtm.y * 31 + vdy.y) << 8) | (vag.y << 18);
            dd0 = vds.x;
            dd1 = vds.y;
        } else {
            int r0 = base + lane * 2, r1 = r0 + 1;
            pk0 = pk1 = dd0 = dd1 = 0;
            if (r0 < n) {
                pk0 = (dow[r0] * 24 + sex[r0] * 12 + month[r0])
                    | ((tim[r0] * 31 + day[r0]) << 8) | (age[r0] << 18);
                dd0 = dest[r0];
            }
            if (r1 < n) {
                pk1 = (dow[r1] * 24 + sex[r1] * 12 + month[r1])
                    | ((tim[r1] * 31 + day[r1]) << 8) | (age[r1] << 18);
                dd1 = dest[r1];
            }
        }
        stw4[lane] = make_uint4((unsigned)pk0, (unsigned)dd0,
                                (unsigned)pk1, (unsigned)dd1);
        __syncwarp();

        // ---- Phase B: 8 steps x 8 rows; rolling item window of depth 4 ----
        uint4 Vs[4];
        int   pkw[4];
        #pragma unroll
        for (int s = 0; s < 4; s++) {
            int2 sd = stw[s * 8 + grp];               // broadcast LDS.64
            pkw[s] = sd.x;
            Vs[s]  = __ldg(&g_itemh[(size_t)sd.y * 4 + sub]);
        }

        #pragma unroll
        for (int s = 0; s < 8; s++) {
            int  pks = pkw[s & 3];
            uint4 V  = Vs[s & 3];
            if (s < 4) {                               // refill slot with s+4
                int2 sd = stw[(s + 4) * 8 + grp];
                pkw[s & 3] = sd.x;
                Vs[s & 3]  = __ldg(&g_itemh[(size_t)sd.y * 4 + sub]);
            }

            int j1 = pks & 255;
            int j2 = N_T1 + ((pks >> 8) & 1023);
            int j3 = N_T1 + N_T2 + ((pks >> 18) & 127);

            // Table entries: each lane reads 16 B (8 halves); conflict-free.
            uint4 A = *reinterpret_cast<const uint4*>(spb + j1 * 128 + par);
            uint4 C = *reinterpret_cast<const uint4*>(spb + j2 * 128 + par);
            uint4 E = *reinterpret_cast<const uint4*>(spb + j3 * 128 + par);

            const __half2* a2 = reinterpret_cast<const __half2*>(&A);
            const __half2* c2 = reinterpret_cast<const __half2*>(&C);
            const __half2* e2 = reinterpret_cast<const __half2*>(&E);
            const __half2* v2 = reinterpret_cast<const __half2*>(&V);

            // Two independent fp16 accumulators; each half accumulates only
            // TWO products (bounded rounding error), final combine in fp32.
            __half2 acc0 = zero2, acc1 = zero2;
            {
                __half2 u0 = __hadd2(__hadd2(a2[0], c2[0]), e2[0]);
                acc0 = __hfma2(u0, v2[0], acc0);
                __half2 u1 = __hadd2(__hadd2(a2[1], c2[1]), e2[1]);
                acc1 = __hfma2(u1, v2[1], acc1);
                __half2 u2 = __hadd2(__hadd2(a2[2], c2[2]), e2[2]);
                acc0 = __hfma2(u2, v2[2], acc0);
                __half2 u3 = __hadd2(__hadd2(a2[3], c2[3]), e2[3]);
                acc1 = __hfma2(u3, v2[3], acc1);
            }
            float2 fa = __half22float2(acc0);
            float2 fb = __half22float2(acc1);
            float p = (fa.x + fa.y) + (fb.x + fb.y);

            // Reduce across the 4-lane group (contiguous lanes) in fp32.
            p += __shfl_xor_sync(0xffffffffu, p, 2);
            p += __shfl_xor_sync(0xffffffffu, p, 1);

            int row = base + s * 8 + grp;
            if (sub == 0 && row < n)
                out[row] = p;     // 8 consecutive rows per step: 1 wavefront
        }
    }
}

extern "C" void kernel_launch(void* const* d_in, const int* in_sizes, int n_in,
                              void* d_out, int out_size) {
    // Input order: dayofweek, time, sex, age, month, day, destination,
    // emb_dow, emb_time, emb_sex, emb_age, emb_month, emb_day, W, b, item_table
    const int* dow   = (const int*)d_in[0];
    const int* tim   = (const int*)d_in[1];
    const int* sex   = (const int*)d_in[2];
    const int* age   = (const int*)d_in[3];
    const int* month = (const int*)d_in[4];
    const int* day   = (const int*)d_in[5];
    const int* dest  = (const int*)d_in[6];
    const float* emb_dow   = (const float*)d_in[7];
    const float* emb_time  = (const float*)d_in[8];
    const float* emb_sex   = (const float*)d_in[9];
    const float* emb_age   = (const float*)d_in[10];
    const float* emb_month = (const float*)d_in[11];
    const float* emb_day   = (const float*)d_in[12];
    const float* W = (const float*)d_in[13];
    const float* b = (const float*)d_in[14];
    const float4* item4f = (const float4*)d_in[15];
    float* out = (float*)d_out;
    int n = in_sizes[0];

    // 1) Fused prep: item fp16 conversion + projected-table build, one launch.
    prep_kernel<<<CV_BLOCKS + PRE_BLOCKS, 256>>>(
        emb_dow, emb_time, emb_sex, emb_age, emb_month, emb_day, W, b, item4f);

    // 2) Main gather + dot kernel. Table 129,536 B + staging 16,384 B smem.
    int smem_bytes = NE * 8 * (int)sizeof(uint4) + 32 * 64 * (int)sizeof(int2);
    cudaFuncSetAttribute(mf_main_kernel,
                         cudaFuncAttributeMaxDynamicSharedMemorySize, smem_bytes);
    mf_main_kernel<<<152, 1024, smem_bytes>>>(
        dow, tim, sex, age, month, day, dest, out, n);
}

// round 13
// speedup vs baseline: 1.0326x; 1.0326x over previous
#include <cuda_runtime.h>
#include <cuda_fp16.h>

#define N_T1 168            // dow(7) * sex(2) * month(12)
#define N_T2 744            // time(24) * day(31)
#define N_T3 100            // age
#define NE   (N_T1 + N_T2 + N_T3)   // 1012
#define NUM_DEST 100000

// Pre-projected fused tables in fp16, DUPLICATED per entry:
// entry e occupies 128 B: copy A at [e*128, e*128+64)    -> smem banks 0..15
//                         copy B at [e*128+64, e*128+128) -> smem banks 16..31
__device__ uint4 g_projh[NE * 8];        // NE * 128 B
// Item table converted to fp16: row = 32 halves = 64 B = 4 uint4.
__device__ uint4 g_itemh[NUM_DEST * 4];  // 6.4 MB

#define CV_THREADS (NUM_DEST * 8)            // one thread per 4 floats
#define CV_BLOCKS  ((CV_THREADS + 255) / 256)
#define PRE_THREADS (NE * 32)
#define PRE_BLOCKS ((PRE_THREADS + 255) / 256)

__global__ __launch_bounds__(256)
void prep_kernel(const float* __restrict__ emb_dow,
                 const float* __restrict__ emb_time,
                 const float* __restrict__ emb_sex,
                 const float* __restrict__ emb_age,
                 const float* __restrict__ emb_month,
                 const float* __restrict__ emb_day,
                 const float* __restrict__ W,
                 const float* __restrict__ b,
                 const float4* __restrict__ item4f) {
    if (blockIdx.x < CV_BLOCKS) {
        // ---- Item table fp32 -> fp16 (one thread per float4) ----
        int t = blockIdx.x * 256 + threadIdx.x;
        if (t >= CV_THREADS) return;
        float4 f = item4f[t];
        __half2 lo = __floats2half2_rn(f.x, f.y);
        __half2 hi = __floats2half2_rn(f.z, f.w);
        reinterpret_cast<uint2*>(g_itemh)[t] =
            make_uint2(*reinterpret_cast<uint*>(&lo), *reinterpret_cast<uint*>(&hi));
        return;
    }
    // ---- Pre-projected fused user tables ----
    int t = (blockIdx.x - CV_BLOCKS) * 256 + threadIdx.x;
    if (t >= PRE_THREADS) return;
    int e = t >> 5;
    int f = t & 31;
    float v = 0.f;
    // W row layout follows concat order: dow[0:4) time[4:8) sex[8:12) age[12:16) month[16:20) day[20:24)
    if (e < N_T1) {
        int d = e / 24, rem = e % 24;
        int s = rem / 12, m = rem % 12;
        #pragma unroll
        for (int j = 0; j < 4; j++) {
            v = fmaf(emb_dow[d * 4 + j],   W[(0 + j) * 32 + f], v);
            v = fmaf(emb_sex[s * 4 + j],   W[(8 + j) * 32 + f], v);
            v = fmaf(emb_month[m * 4 + j], W[(16 + j) * 32 + f], v);
        }
    } else if (e < N_T1 + N_T2) {
        int e2 = e - N_T1;
        int tm = e2 / 31, dy = e2 % 31;
        #pragma unroll
        for (int j = 0; j < 4; j++) {
            v = fmaf(emb_time[tm * 4 + j], W[(4 + j) * 32 + f], v);
            v = fmaf(emb_day[dy * 4 + j],  W[(20 + j) * 32 + f], v);
        }
    } else {
        int a = e - (N_T1 + N_T2);
        v = b[f];
        #pragma unroll
        for (int j = 0; j < 4; j++)
            v = fmaf(emb_age[a * 4 + j], W[(12 + j) * 32 + f], v);
    }
    __half hv = __float2half_rn(v);
    __half* base = reinterpret_cast<__half*>(g_projh) + e * 64;
    base[f]      = hv;   // copy A
    base[32 + f] = hv;   // copy B
}

// Guarded per-lane index load + pack for one 32-row tile.
__device__ __forceinline__ void load_idx(const int* __restrict__ dow,
                                         const int* __restrict__ tim,
                                         const int* __restrict__ sex,
                                         const int* __restrict__ age,
                                         const int* __restrict__ month,
                                         const int* __restrict__ day,
                                         const int* __restrict__ dest,
                                         int base, int lane, int n,
                                         int& pk, int& dd) {
    int r = base + lane;
    pk = 0; dd = 0;
    if (r < n) {
        int i1 = dow[r] * 24 + sex[r] * 12 + month[r];   // 0..167  (8 bits)
        int t2 = tim[r] * 31 + day[r];                   // 0..743  (10 bits)
        int a3 = age[r];                                 // 0..99   (7 bits)
        pk = i1 | (t2 << 8) | (a3 << 18);
        dd = dest[r];
    }
}

__global__ __launch_bounds__(1024, 1)
void mf_main_kernel(const int* __restrict__ dow,
                    const int* __restrict__ tim,
                    const int* __restrict__ sex,
                    const int* __restrict__ age,
                    const int* __restrict__ month,
                    const int* __restrict__ day,
                    const int* __restrict__ dest,
                    float* __restrict__ out,
                    int n) {
    extern __shared__ uint4 sp[];   // table (NE*8 uint4) + per-warp idx staging
    int2* stage = reinterpret_cast<int2*>(sp + NE * 8);   // 32 warps x 32 int2 = 8 KB

    for (int i = threadIdx.x; i < NE * 8; i += blockDim.x)
        sp[i] = g_projh[i];
    __syncthreads();

    const char* spb = reinterpret_cast<const char*>(sp);

    const int lane = threadIdx.x & 31;
    const int warp = threadIdx.x >> 5;
    const int sub  = lane & 3;        // position within 4-lane group (8 halves each)
    const int grp  = lane >> 2;       // group id 0..7 (contiguous lanes)
    // Dup tables: adjacent groups have opposite parity -> each 8-lane LDS phase
    // hits disjoint bank halves: deterministically conflict-free.
    const int par  = (grp & 1) * 64 + sub * 16;

    int2* stw = stage + warp * 32;    // this warp's staging slots

    const int warpsTotal = gridDim.x * (blockDim.x >> 5);
    const int gwarp = blockIdx.x * (blockDim.x >> 5) + warp;
    const int stride = warpsTotal * 32;

    const __half2 zero2 = __float2half2_rn(0.f);

    // Pipeline prologue: indices for the first tile.
    int pk, dd;
    load_idx(dow, tim, sex, age, month, day, dest, gwarp * 32, lane, n, pk, dd);

    for (int base = gwarp * 32; base < n; base += stride) {
        // Stage current tile's indices (loaded last iteration / prologue).
        stw[lane] = make_int2(pk, dd);
        __syncwarp();

        // Prefetch NEXT tile's indices now: the 7 DRAM-latency loads overlap
        // with all of phase B instead of stalling the next iteration's start.
        int nbase = base + stride;
        if (nbase < n)
            load_idx(dow, tim, sex, age, month, day, dest, nbase, lane, n, pk, dd);

        // Batched broadcast reads: all 4 steps' (pk, dd) at once (no chains).
        int2 sd0 = stw[0 * 8 + grp];
        int2 sd1 = stw[1 * 8 + grp];
        int2 sd2 = stw[2 * 8 + grp];
        int2 sd3 = stw[3 * 8 + grp];

        // Batched item loads: 4 independent LDGs in flight (MLP=4).
        uint4 V0 = __ldg(&g_itemh[(size_t)sd0.y * 4 + sub]);
        uint4 V1 = __ldg(&g_itemh[(size_t)sd1.y * 4 + sub]);
        uint4 V2 = __ldg(&g_itemh[(size_t)sd2.y * 4 + sub]);
        uint4 V3 = __ldg(&g_itemh[(size_t)sd3.y * 4 + sub]);

        int pks[4] = {sd0.x, sd1.x, sd2.x, sd3.x};
        uint4 Vs[4] = {V0, V1, V2, V3};

        // Phase B: 4 sub-iterations; each processes 8 rows with 4 lanes/row.
        #pragma unroll
        for (int s = 0; s < 4; s++) {
            int j1 = pks[s] & 255;
            int j2 = N_T1 + ((pks[s] >> 8) & 1023);
            int j3 = N_T1 + N_T2 + ((pks[s] >> 18) & 127);

            // Table entries: each lane reads 16 B (8 halves); conflict-free.
            uint4 A = *reinterpret_cast<const uint4*>(spb + j1 * 128 + par);
            uint4 C = *reinterpret_cast<const uint4*>(spb + j2 * 128 + par);
            uint4 E = *reinterpret_cast<const uint4*>(spb + j3 * 128 + par);

            const __half2* a2 = reinterpret_cast<const __half2*>(&A);
            const __half2* c2 = reinterpret_cast<const __half2*>(&C);
            const __half2* e2 = reinterpret_cast<const __half2*>(&E);
            const __half2* v2 = reinterpret_cast<const __half2*>(&Vs[s]);

            // Two independent fp16 accumulators; each half accumulates only
            // TWO products (bounded rounding error), final combine in fp32.
            __half2 acc0 = zero2, acc1 = zero2;
            {
                __half2 u0 = __hadd2(__hadd2(a2[0], c2[0]), e2[0]);
                acc0 = __hfma2(u0, v2[0], acc0);
                __half2 u1 = __hadd2(__hadd2(a2[1], c2[1]), e2[1]);
                acc1 = __hfma2(u1, v2[1], acc1);
                __half2 u2 = __hadd2(__hadd2(a2[2], c2[2]), e2[2]);
                acc0 = __hfma2(u2, v2[2], acc0);
                __half2 u3 = __hadd2(__hadd2(a2[3], c2[3]), e2[3]);
                acc1 = __hfma2(u3, v2[3], acc1);
            }
            float2 fa = __half22float2(acc0);
            float2 fb = __half22float2(acc1);
            float p = (fa.x + fa.y) + (fb.x + fb.y);

            // Reduce across the 4-lane group (contiguous lanes) in fp32.
            p += __shfl_xor_sync(0xffffffffu, p, 2);
            p += __shfl_xor_sync(0xffffffffu, p, 1);

            int row = base + s * 8 + grp;
            if (sub == 0 && row < n)
                out[row] = p;     // 8 consecutive rows per step: 1 wavefront
        }
        // All staged reads for this tile are done (reads above); safe to
        // overwrite staging at the next iteration's top after __syncwarp.
        __syncwarp();
    }
}

extern "C" void kernel_launch(void* const* d_in, const int* in_sizes, int n_in,
                              void* d_out, int out_size) {
    // Input order: dayofweek, time, sex, age, month, day, destination,
    // emb_dow, emb_time, emb_sex, emb_age, emb_month, emb_day, W, b, item_table
    const int* dow   = (const int*)d_in[0];
    const int* tim   = (const int*)d_in[1];
    const int* sex   = (const int*)d_in[2];
    const int* age   = (const int*)d_in[3];
    const int* month = (const int*)d_in[4];
    const int* day   = (const int*)d_in[5];
    const int* dest  = (const int*)d_in[6];
    const float* emb_dow   = (const float*)d_in[7];
    const float* emb_time  = (const float*)d_in[8];
    const float* emb_sex   = (const float*)d_in[9];
    const float* emb_age   = (const float*)d_in[10];
    const float* emb_month = (const float*)d_in[11];
    const float* emb_day   = (const float*)d_in[12];
    const float* W = (const float*)d_in[13];
    const float* b = (const float*)d_in[14];
    const float4* item4f = (const float4*)d_in[15];
    float* out = (float*)d_out;
    int n = in_sizes[0];

    // 1) Fused prep: item fp16 conversion + projected-table build, one launch.
    prep_kernel<<<CV_BLOCKS + PRE_BLOCKS, 256>>>(
        emb_dow, emb_time, emb_sex, emb_age, emb_month, emb_day, W, b, item4f);

    // 2) Main gather + dot kernel. Table 129,536 B + staging 8,192 B smem.
    int smem_bytes = NE * 8 * (int)sizeof(uint4) + 32 * 32 * (int)sizeof(int2);
    cudaFuncSetAttribute(mf_main_kernel,
                         cudaFuncAttributeMaxDynamicSharedMemorySize, smem_bytes);
    mf_main_kernel<<<152, 1024, smem_bytes>>>(
        dow, tim, sex, age, month, day, dest, out, n);
}